// round 16
// baseline (speedup 1.0000x reference)
#include <cuda_runtime.h>
#include <cuda_fp16.h>
#include <cstdint>

// Problem constants (ResNHConv_274877907666): B=1, N=196608, NH=9, F=64.
#define F_DIM    64
#define NH_DIM   9
#define MAX_N    196608
#define TILE_M   256
#define NTHREADS 256
#define NWARPS   8
#define RPW      32          // rows per warp
#define NBUF     4           // pipeline depth (A buffers per warp)

// ---------------- smem layout (bytes) ----------------
// B = W^T as fp16, plain K-major: [n=64] rows of 584 halves (1168 B each;
// 292 words ≡ 4 mod 32 -> conflict-free 8-row LDSM pattern).
#define B_ROW_B    1168
#define SM_B       0
#define SM_B_SIZE  (F_DIM * B_ROW_B)                 // 74752
// A: per-warp private fp16 rows, 32 rows x 144B (36 words ≡ 4 mod 32),
// 4-deep: 8 warps x 4 x 4608 = 147456
#define A_STRIDE_B 144
#define A_WBUF_B   (RPW * A_STRIDE_B)                // 4608
#define SM_A       SM_B_SIZE                         // 74752
#define SM_BIAS    (SM_A + NWARPS * NBUF * A_WBUF_B) // 222208
#define SM_LW      (SM_BIAS + 256)
#define SM_LB      (SM_LW + 256)
#define SM_TOTAL   (SM_LB + 256)                     // 222976 < 227KB limit

// Scratch buffers as uint4 for 16B alignment (cp.async sources).
__device__ uint4 g_h1[(size_t)MAX_N * F_DIM / 8];
__device__ uint4 g_h2[(size_t)MAX_N * F_DIM / 8];

// ---------------- PTX helpers ----------------
__device__ __forceinline__ uint32_t smem_u32(const void* p) {
    uint32_t a;
    asm("{ .reg .u64 t; cvta.to.shared.u64 t, %1; cvt.u32.u64 %0, t; }" : "=r"(a) : "l"(p));
    return a;
}
#define LDSM4(r, addr) \
    asm volatile("ldmatrix.sync.aligned.m8n8.x4.shared.b16 {%0,%1,%2,%3}, [%4];" \
        : "=r"((r)[0]), "=r"((r)[1]), "=r"((r)[2]), "=r"((r)[3]) : "r"(addr))
__device__ __forceinline__ void cp16(uint32_t dst, const void* src) {
    asm volatile("cp.async.cg.shared.global [%0], [%1], 16;" :: "r"(dst), "l"(src) : "memory");
}
__device__ __forceinline__ void cp_commit() {
    asm volatile("cp.async.commit_group;" ::: "memory");
}
template <int N>
__device__ __forceinline__ void cp_wait() {
    asm volatile("cp.async.wait_group %0;" :: "n"(N) : "memory");
}
__device__ __forceinline__ void mma_f16(float* c,
                                        uint32_t a0, uint32_t a1, uint32_t a2, uint32_t a3,
                                        uint32_t b0, uint32_t b1) {
    asm volatile(
        "mma.sync.aligned.m16n8k16.row.col.f32.f16.f16.f32 "
        "{%0,%1,%2,%3}, {%4,%5,%6,%7}, {%8,%9}, {%0,%1,%2,%3};"
        : "+f"(c[0]), "+f"(c[1]), "+f"(c[2]), "+f"(c[3])
        : "r"(a0), "r"(a1), "r"(a2), "r"(a3), "r"(b0), "r"(b1));
}

// ---------------------------------------------------------------------------
// Kernel 1: h1 = silu(layernorm(x)) as fp16.
// 8 lanes per row, 4 rows per warp -> 8 independent LDG.128 in flight/warp.
// ---------------------------------------------------------------------------
__global__ void ln_silu_kernel(const float4* __restrict__ x4,
                               const float4* __restrict__ lnw4,
                               const float4* __restrict__ lnb4,
                               uint4* __restrict__ out4, int N)
{
    const int warp = blockIdx.x * (blockDim.x >> 5) + (threadIdx.x >> 5);
    const int lane = threadIdx.x & 31;
    const int rg   = lane >> 3;          // 0..3 row within warp
    const int li   = lane & 7;           // 0..7 lane within row
    const int row  = warp * 4 + rg;
    if (row >= N) return;

    const float4* xr = x4 + (size_t)row * 16;
    const float4 v0 = xr[2 * li];
    const float4 v1 = xr[2 * li + 1];

    float s  = v0.x + v0.y + v0.z + v0.w + v1.x + v1.y + v1.z + v1.w;
    float s2 = v0.x*v0.x + v0.y*v0.y + v0.z*v0.z + v0.w*v0.w
             + v1.x*v1.x + v1.y*v1.y + v1.z*v1.z + v1.w*v1.w;
    #pragma unroll
    for (int off = 1; off < 8; off <<= 1) {
        s  += __shfl_xor_sync(0xffffffffu, s,  off);
        s2 += __shfl_xor_sync(0xffffffffu, s2, off);
    }
    const float mu  = s * (1.0f / F_DIM);
    const float var = s2 * (1.0f / F_DIM) - mu * mu;
    const float rs  = rsqrtf(var + 1e-5f);

    const float4 w0 = lnw4[2 * li], w1 = lnw4[2 * li + 1];
    const float4 b0 = lnb4[2 * li], b1 = lnb4[2 * li + 1];

    float y[8];
    y[0] = (v0.x - mu) * rs * w0.x + b0.x;
    y[1] = (v0.y - mu) * rs * w0.y + b0.y;
    y[2] = (v0.z - mu) * rs * w0.z + b0.z;
    y[3] = (v0.w - mu) * rs * w0.w + b0.w;
    y[4] = (v1.x - mu) * rs * w1.x + b1.x;
    y[5] = (v1.y - mu) * rs * w1.y + b1.y;
    y[6] = (v1.z - mu) * rs * w1.z + b1.z;
    y[7] = (v1.w - mu) * rs * w1.w + b1.w;

    __half2 h[4];
    #pragma unroll
    for (int i = 0; i < 4; ++i) {
        float o0 = y[2*i]   / (1.0f + expf(-y[2*i]));
        float o1 = y[2*i+1] / (1.0f + expf(-y[2*i+1]));
        h[i] = __floats2half2_rn(o0, o1);
    }
    uint4 pack;
    pack.x = *(uint32_t*)&h[0]; pack.y = *(uint32_t*)&h[1];
    pack.z = *(uint32_t*)&h[2]; pack.w = *(uint32_t*)&h[3];
    out4[(size_t)row * 8 + li] = pack;
}

// ---------------------------------------------------------------------------
// Persistent fp16 mma.sync (m16n8k16) gather-GEMM; warp-private 4-deep pipes.
// 8 warps x 32 rows: each B-LDSM feeds 2 m-frags (16 HMMA) -> B smem traffic
// per output halves vs 16x16 layout.
// FIRST=true : out = fp16(silu(LN(D + bias)))
// FIRST=false: out = fp32(D + bias + xres)
// ---------------------------------------------------------------------------
template <bool FIRST>
__global__ void __launch_bounds__(NTHREADS, 1)
gemm_kernel(const __half* __restrict__ hin,
            const int* __restrict__ adjc,
            const float* __restrict__ W,
            const float* __restrict__ bias,
            const float* __restrict__ lnw,
            const float* __restrict__ lnb,
            const float* __restrict__ xres,
            void* __restrict__ out_v,
            int Nnodes, int n_tiles)
{
    extern __shared__ char smem[];
    const uint32_t sbase = smem_u32(smem);

    const int tid  = threadIdx.x;
    const int wid  = tid >> 5;
    const int lane = tid & 31;
    const int gid  = lane >> 2;    // 0..7
    const int tig  = lane & 3;     // 0..3

    float* sBias = (float*)(smem + SM_BIAS);
    float* sLw   = (float*)(smem + SM_LW);
    float* sLb   = (float*)(smem + SM_LB);

    // ---- stage B = W^T (fp16), plain K-major [n][584] ----
    for (int i = tid; i < NH_DIM * F_DIM * F_DIM; i += NTHREADS) {
        const int head = i >> 12;
        const int rem  = i & 4095;
        const int f    = rem >> 6;
        const int n    = rem & 63;
        const int k    = head * 64 + f;
        *(__half*)(smem + SM_B + n * B_ROW_B + k * 2) = __float2half_rn(W[i]);
    }
    if (tid < F_DIM) {
        sBias[tid] = bias[tid];
        if (FIRST) { sLw[tid] = lnw[tid]; sLb[tid] = lnb[tid]; }
    }
    __syncthreads();   // only CTA-wide sync

    const uint32_t aW = sbase + SM_A + wid * (NBUF * A_WBUF_B);
    const int chunk = lane & 7;             // 16B chunk within 128B row
    const int rsel  = lane >> 3;            // 0..3: row within 4-row pass

    // LDSM lane-address components (constant per thread)
    const uint32_t aLane = (uint32_t)((lane & 15) * A_STRIDE_B + (lane >> 4) * 16);
    const uint32_t bLane = sbase + SM_B
        + (uint32_t)(((lane >> 4) * 8 + (lane & 7)) * B_ROW_B + ((lane >> 3) & 1) * 16);

    for (int tile = blockIdx.x; tile < n_tiles; tile += gridDim.x) {
        const int base_node = tile * TILE_M;

        // lane l holds the 9 neighbor indices of strip-row l (0..31)
        int idxs[NH_DIM];
        {
            const int my_row   = base_node + wid * RPW + lane;
            const int safe_row = my_row < Nnodes ? my_row : Nnodes - 1;
            const int* arow    = adjc + (size_t)safe_row * NH_DIM;
            #pragma unroll
            for (int k = 0; k < NH_DIM; ++k) idxs[k] = arow[k];
        }

        float acc[2][8][4];
        #pragma unroll
        for (int mf = 0; mf < 2; ++mf)
            #pragma unroll
            for (int j = 0; j < 8; ++j)
                #pragma unroll
                for (int c = 0; c < 4; ++c) acc[mf][j][c] = 0.0f;

        __syncwarp();

        // ---- prologue: gathers for heads 0..2 into bufs 0..2 ----
        #pragma unroll
        for (int k0 = 0; k0 < NBUF - 1; ++k0) {
            const uint32_t dstb = aW + k0 * A_WBUF_B;
            #pragma unroll
            for (int i = 0; i < 8; ++i) {
                const int row = 4 * i + rsel;
                const int idx = __shfl_sync(0xffffffffu, idxs[k0], row);
                cp16(dstb + row * A_STRIDE_B + chunk * 16,
                     hin + (size_t)idx * F_DIM + chunk * 8);
            }
            cp_commit();
        }

        for (int k = 0; k < NH_DIM; ++k) {
            if (k + NBUF - 1 < NH_DIM) {
                const int kp = k + NBUF - 1;
                const uint32_t dstb = aW + (kp & (NBUF - 1)) * A_WBUF_B;
                #pragma unroll
                for (int i = 0; i < 8; ++i) {
                    const int row = 4 * i + rsel;
                    const int idx = __shfl_sync(0xffffffffu, idxs[kp], row);
                    cp16(dstb + row * A_STRIDE_B + chunk * 16,
                         hin + (size_t)idx * F_DIM + chunk * 8);
                }
                cp_commit();
            }
            // wait until group k complete: allow min(NBUF-1, NH-1-k) newer pending
            {
                const int pend = (NH_DIM - 1 - k < NBUF - 1) ? (NH_DIM - 1 - k) : (NBUF - 1);
                if      (pend >= 3) cp_wait<3>();
                else if (pend == 2) cp_wait<2>();
                else if (pend == 1) cp_wait<1>();
                else                cp_wait<0>();
            }
            __syncwarp();

            // ---- mma on buf k&(NBUF-1): per kss: 2 A-LDSM + 4 B-LDSM + 16 HMMA ----
            const uint32_t aBase = aW + (k & (NBUF - 1)) * A_WBUF_B + aLane;
            const uint32_t bBase = bLane + (uint32_t)(k * 128);

            #pragma unroll
            for (int kss = 0; kss < 4; ++kss) {
                uint32_t aF0[4], aF1[4];
                LDSM4(aF0, aBase + kss * 32);
                LDSM4(aF1, aBase + 16 * A_STRIDE_B + kss * 32);
                #pragma unroll
                for (int jj = 0; jj < 4; ++jj) {
                    uint32_t bF[4];
                    LDSM4(bF, bBase + jj * (16 * B_ROW_B) + kss * 32);
                    mma_f16(acc[0][2*jj],   aF0[0], aF0[1], aF0[2], aF0[3], bF[0], bF[1]);
                    mma_f16(acc[0][2*jj+1], aF0[0], aF0[1], aF0[2], aF0[3], bF[2], bF[3]);
                    mma_f16(acc[1][2*jj],   aF1[0], aF1[1], aF1[2], aF1[3], bF[0], bF[1]);
                    mma_f16(acc[1][2*jj+1], aF1[0], aF1[1], aF1[2], aF1[3], bF[2], bF[3]);
                }
            }
            __syncwarp();
        }

        // ---- epilogue: registers -> global (warp-private) ----
        #pragma unroll
        for (int mf = 0; mf < 2; ++mf) {
            #pragma unroll
            for (int p = 0; p < 2; ++p) {
                const int r    = wid * RPW + mf * 16 + p * 8 + gid;
                const int node = base_node + r;

                float v[16];
                #pragma unroll
                for (int j = 0; j < 8; ++j) {
                    const int c = j * 8 + tig * 2;
                    v[2*j]   = acc[mf][j][p*2]   + sBias[c];
                    v[2*j+1] = acc[mf][j][p*2+1] + sBias[c + 1];
                }

                if (FIRST) {
                    float s = 0.0f, s2 = 0.0f;
                    #pragma unroll
                    for (int e = 0; e < 16; ++e) { s += v[e]; s2 += v[e] * v[e]; }
                    s  += __shfl_xor_sync(0xffffffffu, s, 1);
                    s2 += __shfl_xor_sync(0xffffffffu, s2, 1);
                    s  += __shfl_xor_sync(0xffffffffu, s, 2);
                    s2 += __shfl_xor_sync(0xffffffffu, s2, 2);
                    const float mu  = s * (1.0f / F_DIM);
                    const float var = s2 * (1.0f / F_DIM) - mu * mu;
                    const float rs  = rsqrtf(var + 1e-5f);
                    if (node < Nnodes) {
                        __half* hout = (__half*)out_v;
                        #pragma unroll
                        for (int j = 0; j < 8; ++j) {
                            const int c = j * 8 + tig * 2;
                            float y0 = (v[2*j]   - mu) * rs * sLw[c]   + sLb[c];
                            float y1 = (v[2*j+1] - mu) * rs * sLw[c+1] + sLb[c+1];
                            float o0 = y0 / (1.0f + expf(-y0));
                            float o1 = y1 / (1.0f + expf(-y1));
                            *(__half2*)(hout + (size_t)node * F_DIM + c) =
                                __floats2half2_rn(o0, o1);
                        }
                    }
                } else {
                    if (node < Nnodes) {
                        float* fout = (float*)out_v;
                        #pragma unroll
                        for (int j = 0; j < 8; ++j) {
                            const int c = j * 8 + tig * 2;
                            const float2 xv = *(const float2*)(xres + (size_t)node * F_DIM + c);
                            float2 o;
                            o.x = v[2*j]   + xv.x;
                            o.y = v[2*j+1] + xv.y;
                            *(float2*)(fout + (size_t)node * F_DIM + c) = o;
                        }
                    }
                }
            }
        }
    }
}

// ---------------------------------------------------------------------------
// Launch
// ---------------------------------------------------------------------------
extern "C" void kernel_launch(void* const* d_in, const int* in_sizes, int n_in,
                              void* d_out, int out_size)
{
    const float* x     = (const float*)d_in[0];
    const int*   adjc  = (const int*)d_in[1];     // int32 (JAX x64 disabled)
    const float* ln1_w = (const float*)d_in[2];
    const float* ln1_b = (const float*)d_in[3];
    const float* W1    = (const float*)d_in[4];
    const float* b1    = (const float*)d_in[5];
    const float* ln2_w = (const float*)d_in[6];
    const float* ln2_b = (const float*)d_in[7];
    const float* W2    = (const float*)d_in[8];
    const float* b2    = (const float*)d_in[9];

    const int N = in_sizes[0] / F_DIM;   // B=1
    const int n_tiles = (N + TILE_M - 1) / TILE_M;

    __half* h1 = nullptr;
    __half* h2 = nullptr;
    cudaGetSymbolAddress((void**)&h1, g_h1);
    cudaGetSymbolAddress((void**)&h2, g_h2);

    cudaFuncSetAttribute(gemm_kernel<true>,
                         cudaFuncAttributeMaxDynamicSharedMemorySize, SM_TOTAL);
    cudaFuncSetAttribute(gemm_kernel<false>,
                         cudaFuncAttributeMaxDynamicSharedMemorySize, SM_TOTAL);

    // 1) h1 = fp16(silu(LN(x)))  — 32 rows per 256-thread block
    {
        const int grid = (N + 31) / 32;
        ln_silu_kernel<<<grid, 256>>>((const float4*)x, (const float4*)ln1_w,
                                      (const float4*)ln1_b, (uint4*)h1, N);
    }
    const int grid = 148;   // 1 big CTA per SM
    // 2) h2 = fp16(silu(LN(gather(h1) @ W1 + b1)))
    gemm_kernel<true><<<grid, NTHREADS, SM_TOTAL>>>(
        h1, adjc, W1, b1, ln2_w, ln2_b, nullptr, h2, N, n_tiles);
    // 3) out = gather(h2) @ W2 + b2 + x
    gemm_kernel<false><<<grid, NTHREADS, SM_TOTAL>>>(
        h2, adjc, W2, b2, nullptr, nullptr, x, d_out, N, n_tiles);
}

// round 17
// speedup vs baseline: 1.2875x; 1.2875x over previous
#include <cuda_runtime.h>
#include <cuda_fp16.h>
#include <cstdint>

// Problem constants (ResNHConv_274877907666): B=1, N=196608, NH=9, F=64.
#define F_DIM    64
#define NH_DIM   9
#define MAX_N    196608
#define NTHREADS 512
#define NWARPS   16
#define RPW      16          // rows per strip (= rows per warp-task)
#define NBUF     4           // pipeline depth (A buffers per warp)

// ---------------- smem layout (bytes) ----------------
// B = W^T as fp16, plain K-major: [n=64] rows of 584 halves (1168 B each;
// 292 words ≡ 4 mod 32 -> conflict-free 8-row LDSM pattern).
#define B_ROW_B    1168
#define SM_B       0
#define SM_B_SIZE  (F_DIM * B_ROW_B)                 // 74752
// A: per-warp private fp16 rows, 16 rows x 144B (36 words ≡ 4 mod 32),
// 4-deep: 16 warps x 4 x 2304 = 147456
#define A_STRIDE_B 144
#define A_WBUF_B   (RPW * A_STRIDE_B)                // 2304
#define SM_A       SM_B_SIZE                         // 74752
#define SM_BIAS    (SM_A + NWARPS * NBUF * A_WBUF_B) // 222208
#define SM_LW      (SM_BIAS + 256)
#define SM_LB      (SM_LW + 256)
#define SM_TOTAL   (SM_LB + 256)                     // 222976 < 227KB limit

// Scratch buffers as uint4 for 16B alignment (cp.async sources).
__device__ uint4 g_h1[(size_t)MAX_N * F_DIM / 8];
__device__ uint4 g_h2[(size_t)MAX_N * F_DIM / 8];
// Work-stealing counters (one per gemm launch); reset by ln_silu each call.
__device__ unsigned int g_ctr[2];

// ---------------- PTX helpers ----------------
__device__ __forceinline__ uint32_t smem_u32(const void* p) {
    uint32_t a;
    asm("{ .reg .u64 t; cvta.to.shared.u64 t, %1; cvt.u32.u64 %0, t; }" : "=r"(a) : "l"(p));
    return a;
}
#define LDSM4(r, addr) \
    asm volatile("ldmatrix.sync.aligned.m8n8.x4.shared.b16 {%0,%1,%2,%3}, [%4];" \
        : "=r"((r)[0]), "=r"((r)[1]), "=r"((r)[2]), "=r"((r)[3]) : "r"(addr))
__device__ __forceinline__ void cp16(uint32_t dst, const void* src) {
    asm volatile("cp.async.cg.shared.global [%0], [%1], 16;" :: "r"(dst), "l"(src) : "memory");
}
__device__ __forceinline__ void cp_commit() {
    asm volatile("cp.async.commit_group;" ::: "memory");
}
template <int N>
__device__ __forceinline__ void cp_wait() {
    asm volatile("cp.async.wait_group %0;" :: "n"(N) : "memory");
}
__device__ __forceinline__ void mma_f16(float* c,
                                        uint32_t a0, uint32_t a1, uint32_t a2, uint32_t a3,
                                        uint32_t b0, uint32_t b1) {
    asm volatile(
        "mma.sync.aligned.m16n8k16.row.col.f32.f16.f16.f32 "
        "{%0,%1,%2,%3}, {%4,%5,%6,%7}, {%8,%9}, {%0,%1,%2,%3};"
        : "+f"(c[0]), "+f"(c[1]), "+f"(c[2]), "+f"(c[3])
        : "r"(a0), "r"(a1), "r"(a2), "r"(a3), "r"(b0), "r"(b1));
}

// ---------------------------------------------------------------------------
// Kernel 1: h1 = silu(layernorm(x)) as fp16. Also resets work-steal counters.
// 8 lanes per row, 4 rows per warp -> 8 independent LDG.128 in flight/warp.
// ---------------------------------------------------------------------------
__global__ void ln_silu_kernel(const float4* __restrict__ x4,
                               const float4* __restrict__ lnw4,
                               const float4* __restrict__ lnb4,
                               uint4* __restrict__ out4, int N)
{
    if (blockIdx.x == 0 && threadIdx.x == 0) { g_ctr[0] = 0; g_ctr[1] = 0; }

    const int warp = blockIdx.x * (blockDim.x >> 5) + (threadIdx.x >> 5);
    const int lane = threadIdx.x & 31;
    const int rg   = lane >> 3;          // 0..3 row within warp
    const int li   = lane & 7;           // 0..7 lane within row
    const int row  = warp * 4 + rg;
    if (row >= N) return;

    const float4* xr = x4 + (size_t)row * 16;
    const float4 v0 = xr[2 * li];
    const float4 v1 = xr[2 * li + 1];

    float s  = v0.x + v0.y + v0.z + v0.w + v1.x + v1.y + v1.z + v1.w;
    float s2 = v0.x*v0.x + v0.y*v0.y + v0.z*v0.z + v0.w*v0.w
             + v1.x*v1.x + v1.y*v1.y + v1.z*v1.z + v1.w*v1.w;
    #pragma unroll
    for (int off = 1; off < 8; off <<= 1) {
        s  += __shfl_xor_sync(0xffffffffu, s,  off);
        s2 += __shfl_xor_sync(0xffffffffu, s2, off);
    }
    const float mu  = s * (1.0f / F_DIM);
    const float var = s2 * (1.0f / F_DIM) - mu * mu;
    const float rs  = rsqrtf(var + 1e-5f);

    const float4 w0 = lnw4[2 * li], w1 = lnw4[2 * li + 1];
    const float4 b0 = lnb4[2 * li], b1 = lnb4[2 * li + 1];

    float y[8];
    y[0] = (v0.x - mu) * rs * w0.x + b0.x;
    y[1] = (v0.y - mu) * rs * w0.y + b0.y;
    y[2] = (v0.z - mu) * rs * w0.z + b0.z;
    y[3] = (v0.w - mu) * rs * w0.w + b0.w;
    y[4] = (v1.x - mu) * rs * w1.x + b1.x;
    y[5] = (v1.y - mu) * rs * w1.y + b1.y;
    y[6] = (v1.z - mu) * rs * w1.z + b1.z;
    y[7] = (v1.w - mu) * rs * w1.w + b1.w;

    __half2 h[4];
    #pragma unroll
    for (int i = 0; i < 4; ++i) {
        float o0 = y[2*i]   / (1.0f + expf(-y[2*i]));
        float o1 = y[2*i+1] / (1.0f + expf(-y[2*i+1]));
        h[i] = __floats2half2_rn(o0, o1);
    }
    uint4 pack;
    pack.x = *(uint32_t*)&h[0]; pack.y = *(uint32_t*)&h[1];
    pack.z = *(uint32_t*)&h[2]; pack.w = *(uint32_t*)&h[3];
    out4[(size_t)row * 8 + li] = pack;
}

// ---------------------------------------------------------------------------
// Persistent fp16 mma.sync (m16n8k16) gather-GEMM; warp-private 4-deep pipes,
// ldmatrix-fed inner loop, warp-level work stealing over 16-row strips.
// FIRST=true : out = fp16(silu(LN(D + bias)))
// FIRST=false: out = fp32(D + bias + xres)
// ---------------------------------------------------------------------------
template <bool FIRST>
__global__ void __launch_bounds__(NTHREADS, 1)
gemm_kernel(const __half* __restrict__ hin,
            const int* __restrict__ adjc,
            const float* __restrict__ W,
            const float* __restrict__ bias,
            const float* __restrict__ lnw,
            const float* __restrict__ lnb,
            const float* __restrict__ xres,
            void* __restrict__ out_v,
            unsigned int* __restrict__ ctr,
            int Nnodes)
{
    extern __shared__ char smem[];
    const uint32_t sbase = smem_u32(smem);

    const int tid  = threadIdx.x;
    const int wid  = tid >> 5;
    const int lane = tid & 31;
    const int gid  = lane >> 2;    // 0..7
    const int tig  = lane & 3;     // 0..3

    float* sBias = (float*)(smem + SM_BIAS);
    float* sLw   = (float*)(smem + SM_LW);
    float* sLb   = (float*)(smem + SM_LB);

    // ---- stage B = W^T (fp16), plain K-major [n][584] ----
    for (int i = tid; i < NH_DIM * F_DIM * F_DIM; i += NTHREADS) {
        const int head = i >> 12;
        const int rem  = i & 4095;
        const int f    = rem >> 6;
        const int n    = rem & 63;
        const int k    = head * 64 + f;
        *(__half*)(smem + SM_B + n * B_ROW_B + k * 2) = __float2half_rn(W[i]);
    }
    if (tid < F_DIM) {
        sBias[tid] = bias[tid];
        if (FIRST) { sLw[tid] = lnw[tid]; sLb[tid] = lnb[tid]; }
    }
    __syncthreads();   // only CTA-wide sync

    const uint32_t aW = sbase + SM_A + wid * (NBUF * A_WBUF_B);
    const int chunk = lane & 7;             // 16B chunk within 128B row
    const int rsel  = lane >> 3;            // 0..3: row within 4-row pass

    // LDSM lane-address components (constant per thread)
    const uint32_t aLane = (uint32_t)((lane & 15) * A_STRIDE_B + (lane >> 4) * 16);
    const uint32_t bLane = sbase + SM_B
        + (uint32_t)(((lane >> 4) * 8 + (lane & 7)) * B_ROW_B + ((lane >> 3) & 1) * 16);

    const int n_strips = (Nnodes + RPW - 1) / RPW;

    for (;;) {
        // ---- warp-level work steal: pop next 16-row strip ----
        unsigned int s;
        if (lane == 0) s = atomicAdd(ctr, 1u);
        s = __shfl_sync(0xffffffffu, s, 0);
        if (s >= (unsigned)n_strips) break;

        const int base_node = (int)s * RPW;

        // lanes 0..15: preload 9 neighbor indices of strip-row (lane&15)
        int idxs[NH_DIM];
        {
            const int my_row   = base_node + (lane & 15);
            const int safe_row = my_row < Nnodes ? my_row : Nnodes - 1;
            const int* arow    = adjc + (size_t)safe_row * NH_DIM;
            #pragma unroll
            for (int k = 0; k < NH_DIM; ++k) idxs[k] = arow[k];
        }

        float acc[8][4];
        #pragma unroll
        for (int j = 0; j < 8; ++j)
            #pragma unroll
            for (int c = 0; c < 4; ++c) acc[j][c] = 0.0f;

        __syncwarp();

        // ---- prologue: gathers for heads 0..2 into bufs 0..2 ----
        #pragma unroll
        for (int k0 = 0; k0 < NBUF - 1; ++k0) {
            const uint32_t dstb = aW + k0 * A_WBUF_B;
            #pragma unroll
            for (int i = 0; i < 4; ++i) {
                const int row = 4 * i + rsel;
                const int idx = __shfl_sync(0xffffffffu, idxs[k0], row);
                cp16(dstb + row * A_STRIDE_B + chunk * 16,
                     hin + (size_t)idx * F_DIM + chunk * 8);
            }
            cp_commit();
        }

        for (int k = 0; k < NH_DIM; ++k) {
            if (k + NBUF - 1 < NH_DIM) {
                const int kp = k + NBUF - 1;
                const uint32_t dstb = aW + (kp & (NBUF - 1)) * A_WBUF_B;
                #pragma unroll
                for (int i = 0; i < 4; ++i) {
                    const int row = 4 * i + rsel;
                    const int idx = __shfl_sync(0xffffffffu, idxs[kp], row);
                    cp16(dstb + row * A_STRIDE_B + chunk * 16,
                         hin + (size_t)idx * F_DIM + chunk * 8);
                }
                cp_commit();
            }
            // wait until group k complete: allow min(NBUF-1, NH-1-k) newer pending
            {
                const int pend = (NH_DIM - 1 - k < NBUF - 1) ? (NH_DIM - 1 - k) : (NBUF - 1);
                if      (pend >= 3) cp_wait<3>();
                else if (pend == 2) cp_wait<2>();
                else if (pend == 1) cp_wait<1>();
                else                cp_wait<0>();
            }
            __syncwarp();

            // ---- mma on buf k&(NBUF-1) : 4 k16-steps x 8 n-tiles ----
            const uint32_t aBase = aW + (k & (NBUF - 1)) * A_WBUF_B + aLane;
            const uint32_t bBase = bLane + (uint32_t)(k * 128);

            #pragma unroll
            for (int kss = 0; kss < 4; ++kss) {
                uint32_t aF[4];
                LDSM4(aF, aBase + kss * 32);
                #pragma unroll
                for (int jj = 0; jj < 4; ++jj) {
                    uint32_t bF[4];
                    LDSM4(bF, bBase + jj * (16 * B_ROW_B) + kss * 32);
                    mma_f16(acc[2*jj],   aF[0], aF[1], aF[2], aF[3], bF[0], bF[1]);
                    mma_f16(acc[2*jj+1], aF[0], aF[1], aF[2], aF[3], bF[2], bF[3]);
                }
            }
            __syncwarp();
        }

        // ---- epilogue: registers -> global (warp-private) ----
        #pragma unroll
        for (int p = 0; p < 2; ++p) {
            const int node = base_node + p * 8 + gid;

            float v[16];
            #pragma unroll
            for (int j = 0; j < 8; ++j) {
                const int c = j * 8 + tig * 2;
                v[2*j]   = acc[j][p*2]   + sBias[c];
                v[2*j+1] = acc[j][p*2+1] + sBias[c + 1];
            }

            if (FIRST) {
                float s0 = 0.0f, s2 = 0.0f;
                #pragma unroll
                for (int e = 0; e < 16; ++e) { s0 += v[e]; s2 += v[e] * v[e]; }
                s0 += __shfl_xor_sync(0xffffffffu, s0, 1);
                s2 += __shfl_xor_sync(0xffffffffu, s2, 1);
                s0 += __shfl_xor_sync(0xffffffffu, s0, 2);
                s2 += __shfl_xor_sync(0xffffffffu, s2, 2);
                const float mu  = s0 * (1.0f / F_DIM);
                const float var = s2 * (1.0f / F_DIM) - mu * mu;
                const float rs  = rsqrtf(var + 1e-5f);
                if (node < Nnodes) {
                    __half* hout = (__half*)out_v;
                    #pragma unroll
                    for (int j = 0; j < 8; ++j) {
                        const int c = j * 8 + tig * 2;
                        float y0 = (v[2*j]   - mu) * rs * sLw[c]   + sLb[c];
                        float y1 = (v[2*j+1] - mu) * rs * sLw[c+1] + sLb[c+1];
                        float o0 = y0 / (1.0f + expf(-y0));
                        float o1 = y1 / (1.0f + expf(-y1));
                        *(__half2*)(hout + (size_t)node * F_DIM + c) =
                            __floats2half2_rn(o0, o1);
                    }
                }
            } else {
                if (node < Nnodes) {
                    float* fout = (float*)out_v;
                    #pragma unroll
                    for (int j = 0; j < 8; ++j) {
                        const int c = j * 8 + tig * 2;
                        const float2 xv = *(const float2*)(xres + (size_t)node * F_DIM + c);
                        float2 o;
                        o.x = v[2*j]   + xv.x;
                        o.y = v[2*j+1] + xv.y;
                        *(float2*)(fout + (size_t)node * F_DIM + c) = o;
                    }
                }
            }
        }
    }
}

// ---------------------------------------------------------------------------
// Launch
// ---------------------------------------------------------------------------
extern "C" void kernel_launch(void* const* d_in, const int* in_sizes, int n_in,
                              void* d_out, int out_size)
{
    const float* x     = (const float*)d_in[0];
    const int*   adjc  = (const int*)d_in[1];     // int32 (JAX x64 disabled)
    const float* ln1_w = (const float*)d_in[2];
    const float* ln1_b = (const float*)d_in[3];
    const float* W1    = (const float*)d_in[4];
    const float* b1    = (const float*)d_in[5];
    const float* ln2_w = (const float*)d_in[6];
    const float* ln2_b = (const float*)d_in[7];
    const float* W2    = (const float*)d_in[8];
    const float* b2    = (const float*)d_in[9];

    const int N = in_sizes[0] / F_DIM;   // B=1

    __half* h1 = nullptr;
    __half* h2 = nullptr;
    unsigned int* ctr = nullptr;
    cudaGetSymbolAddress((void**)&h1, g_h1);
    cudaGetSymbolAddress((void**)&h2, g_h2);
    cudaGetSymbolAddress((void**)&ctr, g_ctr);

    cudaFuncSetAttribute(gemm_kernel<true>,
                         cudaFuncAttributeMaxDynamicSharedMemorySize, SM_TOTAL);
    cudaFuncSetAttribute(gemm_kernel<false>,
                         cudaFuncAttributeMaxDynamicSharedMemorySize, SM_TOTAL);

    // 1) h1 = fp16(silu(LN(x)))  — also zeroes the work-steal counters
    {
        const int grid = (N + 31) / 32;
        ln_silu_kernel<<<grid, 256>>>((const float4*)x, (const float4*)ln1_w,
                                      (const float4*)ln1_b, (uint4*)h1, N);
    }
    const int grid = 148;   // 1 big CTA per SM
    // 2) h2 = fp16(silu(LN(gather(h1) @ W1 + b1)))
    gemm_kernel<true><<<grid, NTHREADS, SM_TOTAL>>>(
        h1, adjc, W1, b1, ln2_w, ln2_b, nullptr, h2, ctr + 0, N);
    // 3) out = gather(h2) @ W2 + b2 + x
    gemm_kernel<false><<<grid, NTHREADS, SM_TOTAL>>>(
        h2, adjc, W2, b2, nullptr, nullptr, x, d_out, ctr + 1, N);
}